// round 15
// baseline (speedup 1.0000x reference)
#include <cuda_runtime.h>
#include <cuda_fp16.h>
#include <cuda_bf16.h>
#include <cstdint>

// Problem constants (DiffusionConv: N=50000, E=800000, C=64, K=3)
#define NMAX 50000
#define EMAX 800000
#define C    64

// -------- device scratch (no allocs; statically zero-initialized) --------
__device__ __align__(16) __half g_xh[NMAX * C];    // fp16 gather sources
__device__ __align__(16) __half g_T1h[NMAX * C];
__device__ __align__(16) __half g_T2h[NMAX * C];
__device__ float g_T3[NMAX * C];                   // fp32 (GEMM input only)
__device__ float g_dinv[NMAX];
__device__ unsigned long long g_dc[NMAX];  // packed: cnt<<40 | Q8.24 weighted deg
__device__ int   g_rowbeg[NMAX];
__device__ int   g_rowend[NMAX];
__device__ int   g_cur[NMAX];
__device__ int   g_total;                  // segment-claim cursor
__device__ unsigned long long g_epack[EMAX];   // (norm<<32)|col

// ---------------- degree+count (single packed atomic) + x->fp16 -------------
__global__ void deg_hist_kernel(const int* __restrict__ row,
                                const float* __restrict__ w,
                                const float* __restrict__ x, int E, int N) {
    int e = blockIdx.x * blockDim.x + threadIdx.x;
    if (e < E) {
        int r = row[e];
        unsigned long long q =
            (unsigned long long)(w[e] * 16777216.0f + 0.5f);   // Q.24
        atomicAdd(&g_dc[r], (1ULL << 40) | q);
    }
    if (e < N * 8) {
        int rrow = e >> 3, ch = (e & 7) << 3;
        const float4* p = (const float4*)(x + (size_t)rrow * C + ch);
        float4 a = p[0], b = p[1];
        __half2 h0 = __floats2half2_rn(a.x, a.y);
        __half2 h1 = __floats2half2_rn(a.z, a.w);
        __half2 h2 = __floats2half2_rn(b.x, b.y);
        __half2 h3 = __floats2half2_rn(b.z, b.w);
        uint4 u;
        u.x = *(unsigned*)&h0; u.y = *(unsigned*)&h1;
        u.z = *(unsigned*)&h2; u.w = *(unsigned*)&h3;
        *(uint4*)(g_xh + (size_t)rrow * C + ch) = u;
    }
}

// ---------------- assign: unordered CSR segment claim + dinv ----------------
__global__ void assign_kernel(int N) {
    __shared__ int wsum[16];
    __shared__ int gbase;
    int tid = threadIdx.x;
    int i = blockIdx.x * 512 + tid;
    int lane = tid & 31, wid = tid >> 5;

    unsigned long long dc = (i < N) ? g_dc[i] : 0ULL;
    int v = (int)(dc >> 40);
    int s = v;
#pragma unroll
    for (int off = 1; off < 32; off <<= 1) {
        int t = __shfl_up_sync(0xffffffffu, s, off);
        if (lane >= off) s += t;
    }
    if (lane == 31) wsum[wid] = s;
    __syncthreads();
    if (wid == 0) {
        int ws = (lane < 16) ? wsum[lane] : 0;
#pragma unroll
        for (int off = 1; off < 16; off <<= 1) {
            int t = __shfl_up_sync(0xffffffffu, ws, off);
            if (lane >= off) ws += t;
        }
        if (lane < 16) wsum[lane] = ws;
    }
    __syncthreads();
    if (tid == 0) gbase = atomicAdd(&g_total, wsum[15]);
    __syncthreads();
    if (i < N) {
        int base = gbase + ((wid > 0) ? wsum[wid - 1] : 0);
        int beg = base + s - v;
        g_rowbeg[i] = beg;
        g_rowend[i] = beg + v;
        g_cur[i] = beg;
        float d = (float)(double)(dc & ((1ULL << 40) - 1)) * (1.0f / 16777216.0f);
        g_dinv[i] = (d > 0.f) ? rsqrtf(d) : 0.f;
    }
}

// ---------------- scatter edges into packed CSR (norm fused) ----------------
__global__ void scatter_kernel(const int* __restrict__ row,
                               const int* __restrict__ col,
                               const float* __restrict__ w, int E, int N) {
    int e = blockIdx.x * blockDim.x + threadIdx.x;
    if (e < E) {
        int r = row[e], c = col[e];
        float nm = g_dinv[r] * w[e] * g_dinv[c];
        int pos = atomicAdd(&g_cur[r], 1);
        unsigned long long p =
            ((unsigned long long)__float_as_uint(nm) << 32) | (unsigned)c;
        g_epack[pos] = p;
    }
    if (e < N) g_dc[e] = 0ULL;
    if (e == 0) g_total = 0;
}

// ---------------- propagate: ONE NODE PER 16-LANE HALF-WARP -----------------
// Lane covers 4 channels of its half's node. Two independent edge streams per
// warp (no cross-half reduce), per-node prologue amortized over 2 nodes,
// unroll-8 -> 16 outstanding loads per lane (2x R13 MLP).
// fp16 gather, fp32 accumulate. Steps 0,1 write fp16; step 2 writes fp32.
__global__ void __launch_bounds__(256, 4) prop_csr_kernel(int step, int N) {
    const __half* __restrict__ src =
        (step == 0) ? g_xh : (step == 1 ? g_T1h : g_T2h);

    int warp = (int)((blockIdx.x * blockDim.x + threadIdx.x) >> 5);
    int lane = threadIdx.x & 31;
    int half = lane >> 4;
    int node = warp * 2 + half;
    if (node >= N) return;
    int ch4 = (lane & 15) << 2;            // 4-channel base for this lane

    int beg = g_rowbeg[node];
    int end = g_rowend[node];

    float a0 = 0.f, a1 = 0.f, a2 = 0.f, a3 = 0.f;
    int e = beg;

    // main: 8 edges per iteration (per half) -> 16 loads in flight per lane
    for (; e + 8 <= end; e += 8) {
        unsigned long long pk[8];
#pragma unroll
        for (int j = 0; j < 8; j++) pk[j] = g_epack[e + j];
        uint2 v[8];
#pragma unroll
        for (int j = 0; j < 8; j++) {
            int c = (int)(unsigned)pk[j];
            v[j] = *(const uint2*)(src + ((size_t)c << 6) + ch4);
        }
#pragma unroll
        for (int j = 0; j < 8; j++) {
            float nm = __uint_as_float((unsigned)(pk[j] >> 32));
            float2 f0 = __half22float2(*(__half2*)&v[j].x);
            float2 f1 = __half22float2(*(__half2*)&v[j].y);
            a0 = fmaf(nm, f0.x, a0); a1 = fmaf(nm, f0.y, a1);
            a2 = fmaf(nm, f1.x, a2); a3 = fmaf(nm, f1.y, a3);
        }
    }
    // tail: one edge at a time
    for (; e < end; e++) {
        unsigned long long p = g_epack[e];
        int c = (int)(unsigned)p;
        float nm = __uint_as_float((unsigned)(p >> 32));
        uint2 v = *(const uint2*)(src + ((size_t)c << 6) + ch4);
        float2 f0 = __half22float2(*(__half2*)&v.x);
        float2 f1 = __half22float2(*(__half2*)&v.y);
        a0 = fmaf(nm, f0.x, a0); a1 = fmaf(nm, f0.y, a1);
        a2 = fmaf(nm, f1.x, a2); a3 = fmaf(nm, f1.y, a3);
    }

    if (step == 2) {
        *(float4*)(g_T3 + ((size_t)node << 6) + ch4) =
            make_float4(a0, a1, a2, a3);
    } else {
        __half* dsth = (step == 0) ? g_T1h : g_T2h;
        __half2 h0 = __floats2half2_rn(a0, a1);
        __half2 h1 = __floats2half2_rn(a2, a3);
        uint2 u;
        u.x = *(unsigned*)&h0; u.y = *(unsigned*)&h1;
        *(uint2*)(dsth + ((size_t)node << 6) + ch4) = u;
    }
}

// ---------------- tf32 tensor-core epilogue: out = sum_s A_s @ W_s ----------
// 256 threads = 8 warps; block tile 128 rows x 64 cols; warp tile 16 x 64.
// mma.sync m16n8k8 tf32, fp32 accumulate. A fragments loaded straight from
// global. W folded + tf32-converted + fragment-permuted into 16KB smem.
// W fold: W0=Tf0, W1=Tb0+Tb1, W2=Tf1+Tb2, W3=Tf2.
__device__ __forceinline__ unsigned f2tf32(float f) {
    unsigned u;
    asm("cvt.rna.tf32.f32 %0, %1;" : "=r"(u) : "f"(f));
    return u;
}

__global__ void out_gemm_kernel(const float* __restrict__ x,
                                const float* __restrict__ tf,
                                const float* __restrict__ tb,
                                float* __restrict__ out, int N) {
    __shared__ float2 sWp[2048];          // 16 KB

    int t = threadIdx.x;
    int lane = t & 31;
    int w = t >> 5;
    int gid = lane >> 2;
    int tig = lane & 3;
    int row0 = blockIdx.x * 128 + w * 16;

    float c[8][4];
#pragma unroll
    for (int n = 0; n < 8; n++)
#pragma unroll
        for (int j = 0; j < 4; j++) c[n][j] = 0.f;

#pragma unroll
    for (int s = 0; s < 4; s++) {
        __syncthreads();
        for (int i = t; i < 2048; i += 256) {
            int chunk = i >> 8;
            int ntile = (i >> 5) & 7;
            int ln = i & 31;
            int k = chunk * 8 + (ln & 3);
            int n = ntile * 8 + (ln >> 2);
            float b0, b1;
            int i0 = k * 64 + n, i1 = (k + 4) * 64 + n;
            if (s == 0)      { b0 = tf[i0];              b1 = tf[i1]; }
            else if (s == 1) { b0 = tb[i0] + tb[4096 + i0];
                               b1 = tb[i1] + tb[4096 + i1]; }
            else if (s == 2) { b0 = tf[4096 + i0] + tb[8192 + i0];
                               b1 = tf[4096 + i1] + tb[8192 + i1]; }
            else             { b0 = tf[8192 + i0];       b1 = tf[8192 + i1]; }
            float2 p;
            p.x = __uint_as_float(f2tf32(b0));
            p.y = __uint_as_float(f2tf32(b1));
            sWp[i] = p;
        }
        __syncthreads();

        int r0 = row0 + gid;
        int r1 = r0 + 8;
        bool v0 = r0 < N, v1 = r1 < N;

#pragma unroll
        for (int chunk = 0; chunk < 8; chunk++) {
            int k = chunk * 8 + tig;
            unsigned a0, a1, a2, a3;
            if (s == 0) {
                a0 = v0 ? f2tf32(x[(size_t)r0 * 64 + k]) : 0u;
                a1 = v1 ? f2tf32(x[(size_t)r1 * 64 + k]) : 0u;
                a2 = v0 ? f2tf32(x[(size_t)r0 * 64 + k + 4]) : 0u;
                a3 = v1 ? f2tf32(x[(size_t)r1 * 64 + k + 4]) : 0u;
            } else if (s == 3) {
                a0 = v0 ? f2tf32(g_T3[(size_t)r0 * 64 + k]) : 0u;
                a1 = v1 ? f2tf32(g_T3[(size_t)r1 * 64 + k]) : 0u;
                a2 = v0 ? f2tf32(g_T3[(size_t)r0 * 64 + k + 4]) : 0u;
                a3 = v1 ? f2tf32(g_T3[(size_t)r1 * 64 + k + 4]) : 0u;
            } else {
                const __half* Ah = (s == 1) ? g_T1h : g_T2h;
                a0 = v0 ? f2tf32(__half2float(Ah[(size_t)r0 * 64 + k])) : 0u;
                a1 = v1 ? f2tf32(__half2float(Ah[(size_t)r1 * 64 + k])) : 0u;
                a2 = v0 ? f2tf32(__half2float(Ah[(size_t)r0 * 64 + k + 4])) : 0u;
                a3 = v1 ? f2tf32(__half2float(Ah[(size_t)r1 * 64 + k + 4])) : 0u;
            }
#pragma unroll
            for (int ntile = 0; ntile < 8; ntile++) {
                float2 b = sWp[(chunk * 8 + ntile) * 32 + lane];
                unsigned b0 = __float_as_uint(b.x);
                unsigned b1 = __float_as_uint(b.y);
                asm("mma.sync.aligned.m16n8k8.row.col.f32.tf32.tf32.f32 "
                    "{%0,%1,%2,%3}, {%4,%5,%6,%7}, {%8,%9}, {%0,%1,%2,%3};"
                    : "+f"(c[ntile][0]), "+f"(c[ntile][1]),
                      "+f"(c[ntile][2]), "+f"(c[ntile][3])
                    : "r"(a0), "r"(a1), "r"(a2), "r"(a3), "r"(b0), "r"(b1));
            }
        }
    }

    int r0 = row0 + gid;
    int r1 = r0 + 8;
#pragma unroll
    for (int ntile = 0; ntile < 8; ntile++) {
        int colb = ntile * 8 + 2 * tig;
        if (r0 < N)
            *(float2*)(out + (size_t)r0 * 64 + colb) =
                make_float2(c[ntile][0], c[ntile][1]);
        if (r1 < N)
            *(float2*)(out + (size_t)r1 * 64 + colb) =
                make_float2(c[ntile][2], c[ntile][3]);
    }
}

// ============================================================================
extern "C" void kernel_launch(void* const* d_in, const int* in_sizes, int n_in,
                              void* d_out, int out_size) {
    const float* x  = (const float*)d_in[0];           // [N, 64]
    const int*   ei = (const int*)d_in[1];             // [2, E]
    const float* ew = (const float*)d_in[2];           // [E]
    const float* tf = (const float*)d_in[3];           // [3, 64, 64]
    const float* tb = (const float*)d_in[4];           // [3, 64, 64]
    float* out = (float*)d_out;

    const int N = in_sizes[0] / C;                     // 50000
    const int E = in_sizes[2];                         // 800000
    const int* row = ei;
    const int* col = ei + E;

    // 1. packed degree+count atomic, x->fp16 ride-along
    deg_hist_kernel<<<(E + 255) / 256, 256>>>(row, ew, x, E, N);

    // 2. unordered CSR segment assignment + dinv
    assign_kernel<<<(N + 511) / 512, 512>>>(N);

    // 3. packed CSR scatter (norm fused) + state re-zero for next call
    scatter_kernel<<<(E + 255) / 256, 256>>>(row, col, ew, E, N);

    // 4. three diffusion steps: one node per 16-lane half-warp
    int warps_needed = (N + 1) / 2;                    // 2 nodes per warp
    int prop_blocks = (warps_needed + 7) / 8;          // 8 warps per block
    prop_csr_kernel<<<prop_blocks, 256>>>(0, N);
    prop_csr_kernel<<<prop_blocks, 256>>>(1, N);
    prop_csr_kernel<<<prop_blocks, 256>>>(2, N);

    // 5. tf32 tensor-core epilogue (theta fold + permute in staging)
    out_gemm_kernel<<<(N + 127) / 128, 256>>>(x, tf, tb, out, N);
}

// round 16
// speedup vs baseline: 1.0833x; 1.0833x over previous
#include <cuda_runtime.h>
#include <cuda_fp16.h>
#include <cuda_bf16.h>
#include <cstdint>

// Problem constants (DiffusionConv: N=50000, E=800000, C=64, K=3)
#define NMAX 50000
#define EMAX 800000
#define C    64

#define GRIDDEP_WAIT() asm volatile("griddepcontrol.wait;" ::: "memory")

// -------- device scratch (no allocs; statically zero-initialized) --------
__device__ __align__(16) __half g_xh[NMAX * C];    // fp16 gather sources
__device__ __align__(16) __half g_T1h[NMAX * C];
__device__ __align__(16) __half g_T2h[NMAX * C];
__device__ float g_T3[NMAX * C];                   // fp32 (GEMM input only)
__device__ float g_dinv[NMAX];
__device__ unsigned long long g_dc[NMAX];  // packed: cnt<<40 | Q8.24 weighted deg
__device__ int   g_rowbeg[NMAX];
__device__ int   g_rowend[NMAX];
__device__ int   g_cur[NMAX];
__device__ int   g_total;                  // segment-claim cursor
__device__ unsigned long long g_epack[EMAX];   // (norm<<32)|col

// ---------------- degree+count (single packed atomic) + x->fp16 -------------
__global__ void deg_hist_kernel(const int* __restrict__ row,
                                const float* __restrict__ w,
                                const float* __restrict__ x, int E, int N) {
    GRIDDEP_WAIT();
    int e = blockIdx.x * blockDim.x + threadIdx.x;
    if (e < E) {
        int r = row[e];
        unsigned long long q =
            (unsigned long long)(w[e] * 16777216.0f + 0.5f);   // Q.24
        atomicAdd(&g_dc[r], (1ULL << 40) | q);
    }
    if (e < N * 8) {
        int rrow = e >> 3, ch = (e & 7) << 3;
        const float4* p = (const float4*)(x + (size_t)rrow * C + ch);
        float4 a = p[0], b = p[1];
        __half2 h0 = __floats2half2_rn(a.x, a.y);
        __half2 h1 = __floats2half2_rn(a.z, a.w);
        __half2 h2 = __floats2half2_rn(b.x, b.y);
        __half2 h3 = __floats2half2_rn(b.z, b.w);
        uint4 u;
        u.x = *(unsigned*)&h0; u.y = *(unsigned*)&h1;
        u.z = *(unsigned*)&h2; u.w = *(unsigned*)&h3;
        *(uint4*)(g_xh + (size_t)rrow * C + ch) = u;
    }
}

// ---------------- assign: unordered CSR segment claim + dinv ----------------
__global__ void assign_kernel(int N) {
    GRIDDEP_WAIT();
    __shared__ int wsum[16];
    __shared__ int gbase;
    int tid = threadIdx.x;
    int i = blockIdx.x * 512 + tid;
    int lane = tid & 31, wid = tid >> 5;

    unsigned long long dc = (i < N) ? g_dc[i] : 0ULL;
    int v = (int)(dc >> 40);
    int s = v;
#pragma unroll
    for (int off = 1; off < 32; off <<= 1) {
        int t = __shfl_up_sync(0xffffffffu, s, off);
        if (lane >= off) s += t;
    }
    if (lane == 31) wsum[wid] = s;
    __syncthreads();
    if (wid == 0) {
        int ws = (lane < 16) ? wsum[lane] : 0;
#pragma unroll
        for (int off = 1; off < 16; off <<= 1) {
            int t = __shfl_up_sync(0xffffffffu, ws, off);
            if (lane >= off) ws += t;
        }
        if (lane < 16) wsum[lane] = ws;
    }
    __syncthreads();
    if (tid == 0) gbase = atomicAdd(&g_total, wsum[15]);
    __syncthreads();
    if (i < N) {
        int base = gbase + ((wid > 0) ? wsum[wid - 1] : 0);
        int beg = base + s - v;
        g_rowbeg[i] = beg;
        g_rowend[i] = beg + v;
        g_cur[i] = beg;
        float d = (float)(double)(dc & ((1ULL << 40) - 1)) * (1.0f / 16777216.0f);
        g_dinv[i] = (d > 0.f) ? rsqrtf(d) : 0.f;
    }
}

// ---------------- scatter edges into packed CSR (norm fused) ----------------
__global__ void scatter_kernel(const int* __restrict__ row,
                               const int* __restrict__ col,
                               const float* __restrict__ w, int E, int N) {
    GRIDDEP_WAIT();
    int e = blockIdx.x * blockDim.x + threadIdx.x;
    if (e < E) {
        int r = row[e], c = col[e];
        float nm = g_dinv[r] * w[e] * g_dinv[c];
        int pos = atomicAdd(&g_cur[r], 1);
        unsigned long long p =
            ((unsigned long long)__float_as_uint(nm) << 32) | (unsigned)c;
        g_epack[pos] = p;
    }
    if (e < N) g_dc[e] = 0ULL;
    if (e == 0) g_total = 0;
}

// ---------------- propagate: QUARTER-WARP gather layout ---------------------
// One warp per node; lane covers 8 channels (16B LDG.128 of the fp16 row);
// quarter q (lanes 8q..8q+7) takes edges beg+q, beg+q+4, ... (stride 4).
// Halves LDG count + L1tex queue pressure vs R13 at same register budget.
// fp32 accumulate; cross-quarter shfl_xor(8,16) reduce; lanes 0-7 store.
// Steps 0,1 write fp16 (next gather source); step 2 writes fp32 (GEMM).
__global__ void __launch_bounds__(256) prop_csr_kernel(int step, int N) {
    GRIDDEP_WAIT();
    const __half* __restrict__ src =
        (step == 0) ? g_xh : (step == 1 ? g_T1h : g_T2h);

    int warp = (int)((blockIdx.x * blockDim.x + threadIdx.x) >> 5);
    if (warp >= N) return;
    int lane = threadIdx.x & 31;
    int q   = lane >> 3;             // quarter: which edge stream
    int ch8 = (lane & 7) << 3;       // 8-channel base within the row

    int beg = g_rowbeg[warp];
    int end = g_rowend[warp];

    float a0 = 0.f, a1 = 0.f, a2 = 0.f, a3 = 0.f;
    float a4 = 0.f, a5 = 0.f, a6 = 0.f, a7 = 0.f;

    int t = beg + q;
    // unroll 2: edges t and t+4 (8 edges per warp-iteration)
    for (; t + 4 < end; t += 8) {
        unsigned long long p0 = g_epack[t];
        unsigned long long p1 = g_epack[t + 4];
        int c0 = (int)(unsigned)p0;
        int c1 = (int)(unsigned)p1;
        uint4 v0 = *(const uint4*)(src + ((size_t)c0 << 6) + ch8);
        uint4 v1 = *(const uint4*)(src + ((size_t)c1 << 6) + ch8);
        float n0 = __uint_as_float((unsigned)(p0 >> 32));
        float n1 = __uint_as_float((unsigned)(p1 >> 32));
        {
            float2 f0 = __half22float2(*(__half2*)&v0.x);
            float2 f1 = __half22float2(*(__half2*)&v0.y);
            float2 f2 = __half22float2(*(__half2*)&v0.z);
            float2 f3 = __half22float2(*(__half2*)&v0.w);
            a0 = fmaf(n0, f0.x, a0); a1 = fmaf(n0, f0.y, a1);
            a2 = fmaf(n0, f1.x, a2); a3 = fmaf(n0, f1.y, a3);
            a4 = fmaf(n0, f2.x, a4); a5 = fmaf(n0, f2.y, a5);
            a6 = fmaf(n0, f3.x, a6); a7 = fmaf(n0, f3.y, a7);
        }
        {
            float2 f0 = __half22float2(*(__half2*)&v1.x);
            float2 f1 = __half22float2(*(__half2*)&v1.y);
            float2 f2 = __half22float2(*(__half2*)&v1.z);
            float2 f3 = __half22float2(*(__half2*)&v1.w);
            a0 = fmaf(n1, f0.x, a0); a1 = fmaf(n1, f0.y, a1);
            a2 = fmaf(n1, f1.x, a2); a3 = fmaf(n1, f1.y, a3);
            a4 = fmaf(n1, f2.x, a4); a5 = fmaf(n1, f2.y, a5);
            a6 = fmaf(n1, f3.x, a6); a7 = fmaf(n1, f3.y, a7);
        }
    }
    if (t < end) {        // at most one leftover edge per quarter
        unsigned long long p = g_epack[t];
        int c = (int)(unsigned)p;
        uint4 v = *(const uint4*)(src + ((size_t)c << 6) + ch8);
        float nm = __uint_as_float((unsigned)(p >> 32));
        float2 f0 = __half22float2(*(__half2*)&v.x);
        float2 f1 = __half22float2(*(__half2*)&v.y);
        float2 f2 = __half22float2(*(__half2*)&v.z);
        float2 f3 = __half22float2(*(__half2*)&v.w);
        a0 = fmaf(nm, f0.x, a0); a1 = fmaf(nm, f0.y, a1);
        a2 = fmaf(nm, f1.x, a2); a3 = fmaf(nm, f1.y, a3);
        a4 = fmaf(nm, f2.x, a4); a5 = fmaf(nm, f2.y, a5);
        a6 = fmaf(nm, f3.x, a6); a7 = fmaf(nm, f3.y, a7);
    }

    // reduce the 4 quarters (lanes with equal lane&7 hold same channels)
#pragma unroll
    for (int off = 8; off <= 16; off <<= 1) {
        a0 += __shfl_xor_sync(0xffffffffu, a0, off);
        a1 += __shfl_xor_sync(0xffffffffu, a1, off);
        a2 += __shfl_xor_sync(0xffffffffu, a2, off);
        a3 += __shfl_xor_sync(0xffffffffu, a3, off);
        a4 += __shfl_xor_sync(0xffffffffu, a4, off);
        a5 += __shfl_xor_sync(0xffffffffu, a5, off);
        a6 += __shfl_xor_sync(0xffffffffu, a6, off);
        a7 += __shfl_xor_sync(0xffffffffu, a7, off);
    }

    if (lane < 8) {
        if (step == 2) {
            *(float4*)(g_T3 + ((size_t)warp << 6) + ch8) =
                make_float4(a0, a1, a2, a3);
            *(float4*)(g_T3 + ((size_t)warp << 6) + ch8 + 4) =
                make_float4(a4, a5, a6, a7);
        } else {
            __half* dsth = (step == 0) ? g_T1h : g_T2h;
            __half2 h0 = __floats2half2_rn(a0, a1);
            __half2 h1 = __floats2half2_rn(a2, a3);
            __half2 h2 = __floats2half2_rn(a4, a5);
            __half2 h3 = __floats2half2_rn(a6, a7);
            uint4 u;
            u.x = *(unsigned*)&h0; u.y = *(unsigned*)&h1;
            u.z = *(unsigned*)&h2; u.w = *(unsigned*)&h3;
            *(uint4*)(dsth + ((size_t)warp << 6) + ch8) = u;
        }
    }
}

// ---------------- tf32 tensor-core epilogue: out = sum_s A_s @ W_s ----------
__device__ __forceinline__ unsigned f2tf32(float f) {
    unsigned u;
    asm("cvt.rna.tf32.f32 %0, %1;" : "=r"(u) : "f"(f));
    return u;
}

__global__ void out_gemm_kernel(const float* __restrict__ x,
                                const float* __restrict__ tf,
                                const float* __restrict__ tb,
                                float* __restrict__ out, int N) {
    GRIDDEP_WAIT();
    __shared__ float2 sWp[2048];          // 16 KB

    int t = threadIdx.x;
    int lane = t & 31;
    int w = t >> 5;
    int gid = lane >> 2;
    int tig = lane & 3;
    int row0 = blockIdx.x * 128 + w * 16;

    float c[8][4];
#pragma unroll
    for (int n = 0; n < 8; n++)
#pragma unroll
        for (int j = 0; j < 4; j++) c[n][j] = 0.f;

#pragma unroll
    for (int s = 0; s < 4; s++) {
        __syncthreads();
        for (int i = t; i < 2048; i += 256) {
            int chunk = i >> 8;
            int ntile = (i >> 5) & 7;
            int ln = i & 31;
            int k = chunk * 8 + (ln & 3);
            int n = ntile * 8 + (ln >> 2);
            float b0, b1;
            int i0 = k * 64 + n, i1 = (k + 4) * 64 + n;
            if (s == 0)      { b0 = tf[i0];              b1 = tf[i1]; }
            else if (s == 1) { b0 = tb[i0] + tb[4096 + i0];
                               b1 = tb[i1] + tb[4096 + i1]; }
            else if (s == 2) { b0 = tf[4096 + i0] + tb[8192 + i0];
                               b1 = tf[4096 + i1] + tb[8192 + i1]; }
            else             { b0 = tf[8192 + i0];       b1 = tf[8192 + i1]; }
            float2 p;
            p.x = __uint_as_float(f2tf32(b0));
            p.y = __uint_as_float(f2tf32(b1));
            sWp[i] = p;
        }
        __syncthreads();

        int r0 = row0 + gid;
        int r1 = r0 + 8;
        bool v0 = r0 < N, v1 = r1 < N;

#pragma unroll
        for (int chunk = 0; chunk < 8; chunk++) {
            int k = chunk * 8 + tig;
            unsigned a0, a1, a2, a3;
            if (s == 0) {
                a0 = v0 ? f2tf32(x[(size_t)r0 * 64 + k]) : 0u;
                a1 = v1 ? f2tf32(x[(size_t)r1 * 64 + k]) : 0u;
                a2 = v0 ? f2tf32(x[(size_t)r0 * 64 + k + 4]) : 0u;
                a3 = v1 ? f2tf32(x[(size_t)r1 * 64 + k + 4]) : 0u;
            } else if (s == 3) {
                a0 = v0 ? f2tf32(g_T3[(size_t)r0 * 64 + k]) : 0u;
                a1 = v1 ? f2tf32(g_T3[(size_t)r1 * 64 + k]) : 0u;
                a2 = v0 ? f2tf32(g_T3[(size_t)r0 * 64 + k + 4]) : 0u;
                a3 = v1 ? f2tf32(g_T3[(size_t)r1 * 64 + k + 4]) : 0u;
            } else {
                const __half* Ah = (s == 1) ? g_T1h : g_T2h;
                a0 = v0 ? f2tf32(__half2float(Ah[(size_t)r0 * 64 + k])) : 0u;
                a1 = v1 ? f2tf32(__half2float(Ah[(size_t)r1 * 64 + k])) : 0u;
                a2 = v0 ? f2tf32(__half2float(Ah[(size_t)r0 * 64 + k + 4])) : 0u;
                a3 = v1 ? f2tf32(__half2float(Ah[(size_t)r1 * 64 + k + 4])) : 0u;
            }
#pragma unroll
            for (int ntile = 0; ntile < 8; ntile++) {
                float2 b = sWp[(chunk * 8 + ntile) * 32 + lane];
                unsigned b0 = __float_as_uint(b.x);
                unsigned b1 = __float_as_uint(b.y);
                asm("mma.sync.aligned.m16n8k8.row.col.f32.tf32.tf32.f32 "
                    "{%0,%1,%2,%3}, {%4,%5,%6,%7}, {%8,%9}, {%0,%1,%2,%3};"
                    : "+f"(c[ntile][0]), "+f"(c[ntile][1]),
                      "+f"(c[ntile][2]), "+f"(c[ntile][3])
                    : "r"(a0), "r"(a1), "r"(a2), "r"(a3), "r"(b0), "r"(b1));
            }
        }
    }

    int r0 = row0 + gid;
    int r1 = r0 + 8;
#pragma unroll
    for (int ntile = 0; ntile < 8; ntile++) {
        int colb = ntile * 8 + 2 * tig;
        if (r0 < N)
            *(float2*)(out + (size_t)r0 * 64 + colb) =
                make_float2(c[ntile][0], c[ntile][1]);
        if (r1 < N)
            *(float2*)(out + (size_t)r1 * 64 + colb) =
                make_float2(c[ntile][2], c[ntile][3]);
    }
}

// ============================================================================
// PDL launch helper: overlap kernel launch latency with predecessor execution.
// Consumers call griddepcontrol.wait before reading predecessor output;
// producers signal at kernel completion (no early trigger -> safe, transitive).
template <typename K, typename... Args>
static void launch_pdl(dim3 grid, dim3 block, K kern, Args... args) {
    cudaLaunchConfig_t cfg = {};
    cfg.gridDim = grid;
    cfg.blockDim = block;
    cfg.stream = 0;
    cudaLaunchAttribute at[1];
    at[0].id = cudaLaunchAttributeProgrammaticStreamSerialization;
    at[0].val.programmaticStreamSerializationAllowed = 1;
    cfg.attrs = at;
    cfg.numAttrs = 1;
    cudaLaunchKernelEx(&cfg, kern, args...);
}

extern "C" void kernel_launch(void* const* d_in, const int* in_sizes, int n_in,
                              void* d_out, int out_size) {
    const float* x  = (const float*)d_in[0];           // [N, 64]
    const int*   ei = (const int*)d_in[1];             // [2, E]
    const float* ew = (const float*)d_in[2];           // [E]
    const float* tf = (const float*)d_in[3];           // [3, 64, 64]
    const float* tb = (const float*)d_in[4];           // [3, 64, 64]
    float* out = (float*)d_out;

    const int N = in_sizes[0] / C;                     // 50000
    const int E = in_sizes[2];                         // 800000
    const int* row = ei;
    const int* col = ei + E;

    // 1. packed degree+count atomic, x->fp16 ride-along
    launch_pdl(dim3((E + 255) / 256), dim3(256), deg_hist_kernel,
               row, ew, x, E, N);

    // 2. unordered CSR segment assignment + dinv
    launch_pdl(dim3((N + 511) / 512), dim3(512), assign_kernel, N);

    // 3. packed CSR scatter (norm fused) + state re-zero for next call
    launch_pdl(dim3((E + 255) / 256), dim3(256), scatter_kernel,
               row, col, ew, E, N);

    // 4. three diffusion steps: quarter-warp gather layout
    int prop_blocks = (N + 7) / 8;                     // one warp per node
    launch_pdl(dim3(prop_blocks), dim3(256), prop_csr_kernel, 0, N);
    launch_pdl(dim3(prop_blocks), dim3(256), prop_csr_kernel, 1, N);
    launch_pdl(dim3(prop_blocks), dim3(256), prop_csr_kernel, 2, N);

    // 5. tf32 tensor-core epilogue (theta fold + permute in staging)
    launch_pdl(dim3((N + 127) / 128), dim3(256), out_gemm_kernel,
               x, tf, tb, out, N);
}